// round 14
// baseline (speedup 1.0000x reference)
#include <cuda_runtime.h>
#include <cuda_fp16.h>
#include <stdint.h>

#define BG 32
#define PN 1024
#define FF 512
#define CC 512

// ---------------------------------------------------------------------------
// Static device scratch: fp16 operand copies (all k-stride = 1024).
// ---------------------------------------------------------------------------
__device__ __half g_Eh [(size_t)BG * PN * PN];  // E   [b][n][p]  (gemm2 A)
__device__ __half g_ETh[(size_t)BG * PN * PN];  // E^T [b][p][n]  (gemm1 B)
__device__ __half g_XTh[(size_t)BG * FF * PN];  // X^T [b][f][n]  (gemm1 A)
__device__ __half g_GTh[(size_t)BG * FF * PN];  // GFT^T [b][f][p] (gemm2 B)

// ---------------------------------------------------------------------------
__device__ __forceinline__ uint32_t smem_u32(const void* p) {
    uint32_t a;
    asm("{ .reg .u64 t; cvta.to.shared.u64 t, %1; cvt.u32.u64 %0, t; }" : "=r"(a) : "l"(p));
    return a;
}
__device__ __forceinline__ void cp16(uint32_t dst, const void* src) {
    asm volatile("{ .reg .u64 g; cvta.to.global.u64 g, %1; "
                 "cp.async.cg.shared.global [%0], [g], 16; }"
                 :: "r"(dst), "l"(src) : "memory");
}
#define CP_COMMIT() asm volatile("cp.async.commit_group;" ::: "memory")
#define CP_WAIT(n)  asm volatile("cp.async.wait_group %0;" :: "n"(n) : "memory")

// evict-first (streaming) stores for write-once outputs
__device__ __forceinline__ void stcs_f2(float* p, float2 v) {
    asm volatile("st.global.cs.v2.f32 [%0], {%1, %2};" :: "l"(p), "f"(v.x), "f"(v.y) : "memory");
}
__device__ __forceinline__ void stcs_f1(float* p, float v) {
    asm volatile("st.global.cs.f32 [%0], %1;" :: "l"(p), "f"(v) : "memory");
}
__device__ __forceinline__ void stcs_u4(void* p, uint4 v) {
    asm volatile("st.global.cs.v4.u32 [%0], {%1, %2, %3, %4};"
                 :: "l"(p), "r"(v.x), "r"(v.y), "r"(v.z), "r"(v.w) : "memory");
}

__device__ __forceinline__ void ldsm_x4(uint32_t* r, uint32_t addr) {
    asm volatile("ldmatrix.sync.aligned.m8n8.x4.shared.b16 {%0,%1,%2,%3}, [%4];"
                 : "=r"(r[0]), "=r"(r[1]), "=r"(r[2]), "=r"(r[3]) : "r"(addr));
}
__device__ __forceinline__ void mma16816(float* d, const uint32_t* a,
                                         uint32_t b0, uint32_t b1) {
    asm volatile("mma.sync.aligned.m16n8k16.row.col.f32.f16.f16.f32 "
                 "{%0,%1,%2,%3}, {%4,%5,%6,%7}, {%8,%9}, {%0,%1,%2,%3};"
                 : "+f"(d[0]), "+f"(d[1]), "+f"(d[2]), "+f"(d[3])
                 : "r"(a[0]), "r"(a[1]), "r"(a[2]), "r"(a[3]), "r"(b0), "r"(b1));
}

// SMEM: 3-stage pipeline; per stage 2 tiles (A, B); tile = 128 rows x 32 fp16,
// padded row stride 80B (conflict-free ldmatrix).
#define RS      80
#define TILE_B  (128 * RS)          // 10240
#define STAGE_B (2 * TILE_B)        // 20480
#define SMEM_BYTES (3 * STAGE_B + 256)

// load one k32 stage: 2 tiles of 128x32 fp16 (gmem row stride 1024 elems)
__device__ __forceinline__ void stage_load(uint32_t sb,
                                           const __half* A, const __half* B,
                                           int k0, int tid) {
    const int r = tid >> 2;          // 0..63
    const int q = tid & 3;           // 16B chunk within 64B row
    const int co = k0 + q * 8;
    #pragma unroll
    for (int h = 0; h < 2; ++h) {
        const int row = r + h * 64;
        const uint32_t so = row * RS + q * 16;
        cp16(sb + 0 * TILE_B + so, A + (size_t)row * 1024 + co);
        cp16(sb + 1 * TILE_B + so, B + (size_t)row * 1024 + co);
    }
}

// one 32-k chunk of single-pass fp16 MMA; warp tile 64(m) x 32(n).
__device__ __forceinline__ void compute_chunk(float acc[4][4][4], uint32_t st,
                                              int m0w, int n0w, int lane) {
    const int lrow = lane & 15;
    const int lcol8 = (lane >> 4) << 3;
    #pragma unroll
    for (int ks = 0; ks < 2; ++ks) {
        const uint32_t cofs = (uint32_t)(ks * 16 + lcol8) * 2;
        uint32_t bh[2][4];
        #pragma unroll
        for (int g = 0; g < 2; ++g)
            ldsm_x4(bh[g], st + TILE_B + (uint32_t)(n0w + g * 16 + lrow) * RS + cofs);
        #pragma unroll
        for (int mi = 0; mi < 4; ++mi) {
            uint32_t ah[4];
            ldsm_x4(ah, st + (uint32_t)(m0w + mi * 16 + lrow) * RS + cofs);
            #pragma unroll
            for (int ni = 0; ni < 4; ++ni) {
                const int g = ni >> 1, o = ni & 1;
                mma16816(acc[mi][ni], ah, bh[g][o], bh[g][o + 2]);
            }
        }
    }
}

// ---------------------------------------------------------------------------
// convE: fp32 E -> fp16 Eh + fp16 ETh, AND fused gather for updated_evectors.
// ---------------------------------------------------------------------------
__global__ void k_convE(const float* __restrict__ E,
                        const int* __restrict__ nv, float* __restrict__ out3) {
    __shared__ float s[32][33];
    const int b = blockIdx.z, n0 = blockIdx.y * 32, p0 = blockIdx.x * 32;
    const int tx = threadIdx.x, ty = threadIdx.y;   // (16, 32)
    float2 v = *(const float2*)(E + ((size_t)b * PN + n0 + ty) * PN + p0 + 2 * tx);
    s[ty][2 * tx] = v.x; s[ty][2 * tx + 1] = v.y;
    size_t off = ((size_t)b * PN + n0 + ty) * PN + p0 + 2 * tx;
    *(__half2*)(g_Eh + off) = __halves2half2(__float2half_rn(v.x), __float2half_rn(v.y));
    __syncthreads();
    float a0 = s[2 * tx][ty], a1 = s[2 * tx + 1][ty];
    size_t off2 = ((size_t)b * PN + p0 + ty) * PN + n0 + 2 * tx;
    *(__half2*)(g_ETh + off2) = __halves2half2(__float2half_rn(a0), __float2half_rn(a1));

    // fused gather (warp wid = candidate slot, lane = n offset)
    const int tid = ty * 16 + tx;
    const int wid = tid >> 5, lane = tid & 31;      // 16 warps
    const float stepv = __fdiv_rn((float)nv[b] - 1.0f, 511.0f);
    int c_lo = (int)floorf(((float)p0 - 1.0f) / stepv) - 1;
    if (c_lo < 0) c_lo = 0;
    int c_hi = (int)ceilf(((float)p0 + 32.0f) / stepv) + 2;
    if (c_hi > CC) c_hi = CC;
    for (int c = c_lo + wid; c < c_hi; c += 16) {
        const int idx = (int)rintf(__fmul_rn((float)c, stepv));
        if (idx >= p0 && idx < p0 + 32)
            stcs_f1(out3 + ((size_t)b * CC + c) * PN + n0 + lane, s[lane][idx - p0]);
    }
}
__global__ void k_convX(const float* __restrict__ X,
                        float* __restrict__ out0, float* __restrict__ out2) {
    __shared__ float s[32][33];
    const int b = blockIdx.z, n0 = blockIdx.y * 32, f0 = blockIdx.x * 32;
    const int tx = threadIdx.x, ty = threadIdx.y;
    const size_t xin = ((size_t)b * PN + n0 + ty) * FF + f0 + 2 * tx;
    float2 v = *(const float2*)(X + xin);
    s[ty][2 * tx] = v.x; s[ty][2 * tx + 1] = v.y;
    // fused copies: n_level_feat and original_x (x3), streaming stores
    stcs_f2(out0 + xin, v);
    const size_t rep = ((size_t)b * 3 * PN + n0 + ty) * FF + f0 + 2 * tx;
    stcs_f2(out2 + rep, v);
    stcs_f2(out2 + rep + (size_t)PN * FF, v);
    stcs_f2(out2 + rep + (size_t)2 * PN * FF, v);
    __syncthreads();
    float a0 = s[2 * tx][ty], a1 = s[2 * tx + 1][ty];
    size_t off2 = ((size_t)b * FF + f0 + ty) * PN + n0 + 2 * tx;
    *(__half2*)(g_XTh + off2) = __halves2half2(__float2half_rn(a0), __float2half_rn(a1));
}

// ---------------------------------------------------------------------------
// GEMM1: GT[b][f][p] = sum_n XT[f][n] * ET[p][n]   (m=f, n=p, k=n)
// 3-stage pipeline, one __syncthreads per chunk.
// ---------------------------------------------------------------------------
__global__ __launch_bounds__(256, 2)
void k_gemm1(const int* __restrict__ nv) {
    extern __shared__ char dsm[];
    const uint32_t raw = smem_u32(dsm);
    const uint32_t sb = (raw + 127u) & ~127u;
    const int b = blockIdx.z, f0 = blockIdx.y * 128, p0 = blockIdx.x * 128;
    const int N = nv[b];
    const int tid = threadIdx.x, wid = tid >> 5, lane = tid & 31;
    const int m0w = (wid & 1) * 64, n0w = (wid >> 1) * 32;

    if (p0 >= N) {  // ET rows zero -> GT tile zero
        const uint4 z = make_uint4(0, 0, 0, 0);
        #pragma unroll
        for (int q = 0; q < 8; ++q) {
            int e = q * 256 + tid;
            int r = e >> 4, cchunk = e & 15;
            *(uint4*)(g_GTh + ((size_t)b * FF + f0 + r) * PN + p0 + cchunk * 8) = z;
        }
        return;
    }

    const __half* A = g_XTh + ((size_t)b * FF + f0) * PN;
    const __half* B = g_ETh + ((size_t)b * PN + p0) * PN;
    const int T = (N + 31) >> 5;

    stage_load(sb, A, B, 0, tid); CP_COMMIT();
    if (T > 1) stage_load(sb + STAGE_B, A, B, 32, tid);
    CP_COMMIT();

    float acc[4][4][4];
    #pragma unroll
    for (int i = 0; i < 4; ++i)
        #pragma unroll
        for (int j = 0; j < 4; ++j)
            #pragma unroll
            for (int r = 0; r < 4; ++r) acc[i][j][r] = 0.0f;

    int cur = 0, nxt = 2;   // stage indices mod 3
    for (int t = 0; t < T; ++t) {
        CP_WAIT(1);
        __syncthreads();   // all warps done with stage (t-1); stage t resident
        if (t + 2 < T) stage_load(sb + nxt * STAGE_B, A, B, (t + 2) << 5, tid);
        CP_COMMIT();
        compute_chunk(acc, sb + cur * STAGE_B, m0w, n0w, lane);
        cur = (cur == 2) ? 0 : cur + 1;
        nxt = (nxt == 2) ? 0 : nxt + 1;
    }

    #pragma unroll
    for (int mi = 0; mi < 4; ++mi)
        #pragma unroll
        for (int ni = 0; ni < 4; ++ni)
            #pragma unroll
            for (int h = 0; h < 2; ++h) {
                const int f = f0 + m0w + mi * 16 + (lane >> 2) + h * 8;
                const int p = p0 + n0w + ni * 8 + (lane & 3) * 2;
                const float c0 = acc[mi][ni][h * 2], c1 = acc[mi][ni][h * 2 + 1];
                *(__half2*)(g_GTh + ((size_t)b * FF + f) * PN + p) =
                    __halves2half2(__float2half_rn(c0), __float2half_rn(c1));
            }
}

// ---------------------------------------------------------------------------
// GEMM2 (R12 three-split form): out1[bz][n][f] = sum_{p in [lo,hi)} E[n][p]*GT[f][p]
// ---------------------------------------------------------------------------
__global__ __launch_bounds__(256, 2)
void k_gemm2(const int* __restrict__ nv, float* __restrict__ out1) {
    extern __shared__ char dsm[];
    const int bz = blockIdx.z;
    const int b = bz / 3, kid = bz - b * 3;
    const int n0 = blockIdx.y * 128, f0 = blockIdx.x * 128;
    const int N = nv[b];
    const int tid = threadIdx.x, wid = tid >> 5, lane = tid & 31;

    if (n0 >= N) {  // zero tile
        const uint4 z = make_uint4(0, 0, 0, 0);
        #pragma unroll
        for (int q = 0; q < 16; ++q) {
            int e = q * 256 + tid;
            int r = e >> 5, cchunk = e & 31;
            stcs_u4(out1 + ((size_t)bz * PN + n0 + r) * FF + f0 + cchunk * 4, z);
        }
        return;
    }

    const float nf = (float)N;
    const int s1 = (int)ceilf(__fmul_rn(nf, 0.1f));
    const int s2 = (int)ceilf(__fmul_rn(__fmul_rn(nf, 0.1f), 2.0f));
    const int lo = (kid == 0) ? 0  : (kid == 1 ? s1      : s1 + s2);
    const int hi = (kid == 0) ? s1 : (kid == 1 ? s1 + s2 : N);
    const int kstart = lo & ~31;
    const int T = (hi - kstart + 31) >> 5;

    const uint32_t raw = smem_u32(dsm);
    const uint32_t sb = (raw + 127u) & ~127u;
    const int m0w = (wid & 1) * 64, n0w = (wid >> 1) * 32;

    const __half* A = g_Eh  + ((size_t)b * PN + n0) * PN;
    const __half* B = g_GTh + ((size_t)b * FF + f0) * PN;

    stage_load(sb, A, B, kstart, tid); CP_COMMIT();
    if (T > 1) stage_load(sb + STAGE_B, A, B, kstart + 32, tid);
    CP_COMMIT();

    float acc[4][4][4];
    #pragma unroll
    for (int i = 0; i < 4; ++i)
        #pragma unroll
        for (int j = 0; j < 4; ++j)
            #pragma unroll
            for (int r = 0; r < 4; ++r) acc[i][j][r] = 0.0f;

    int cur = 0, nxt = 2;
    for (int t = 0; t < T; ++t) {
        CP_WAIT(1);
        __syncthreads();
        if (t + 2 < T) stage_load(sb + nxt * STAGE_B, A, B, kstart + ((t + 2) << 5), tid);
        CP_COMMIT();
        const int kg0 = kstart + (t << 5);
        // mask B (one zero factor suffices) at the [lo,hi) edges
        if (kg0 < lo || kg0 + 32 > hi) {
            const uint32_t st = sb + cur * STAGE_B;
            for (int e = tid; e < 128 * 32; e += 256) {
                const int r = e >> 5, c = e & 31;
                const int k = kg0 + c;
                if (k < lo || k >= hi) {
                    const uint32_t a = st + TILE_B + (uint32_t)r * RS + c * 2;
                    asm volatile("st.shared.u16 [%0], 0;" :: "r"(a) : "memory");
                }
            }
            __syncthreads();
        }
        compute_chunk(acc, sb + cur * STAGE_B, m0w, n0w, lane);
        cur = (cur == 2) ? 0 : cur + 1;
        nxt = (nxt == 2) ? 0 : nxt + 1;
    }

    #pragma unroll
    for (int mi = 0; mi < 4; ++mi)
        #pragma unroll
        for (int ni = 0; ni < 4; ++ni)
            #pragma unroll
            for (int h = 0; h < 2; ++h) {
                const int n = n0 + m0w + mi * 16 + (lane >> 2) + h * 8;
                const int f = f0 + n0w + ni * 8 + (lane & 3) * 2;
                float2 v = make_float2(acc[mi][ni][h * 2], acc[mi][ni][h * 2 + 1]);
                stcs_f2(out1 + ((size_t)bz * PN + n) * FF + f, v);
            }
}

// ---------------------------------------------------------------------------
extern "C" void kernel_launch(void* const* d_in, const int* in_sizes, int n_in,
                              void* d_out, int out_size) {
    const float* x = nullptr;
    const float* evec = nullptr;
    const int*   nv = nullptr;
    for (int i = 0; i < n_in; ++i) {
        if      (in_sizes[i] == BG * PN * FF) x    = (const float*)d_in[i];
        else if (in_sizes[i] == BG * PN * PN) evec = (const float*)d_in[i];
        else if (in_sizes[i] == BG)           nv   = (const int*)d_in[i];
    }
    float* out  = (float*)d_out;
    float* out0 = out;                              // n_level_feat  [B,P,F]
    float* out1 = out0 + (size_t)BG * PN * FF;      // x_updated     [B,3,P,F]
    float* out2 = out1 + (size_t)BG * 3 * PN * FF;  // original_x    [B,3,P,F]
    float* out3 = out2 + (size_t)BG * 3 * PN * FF;  // updated_evecs [B,C,P]

    cudaFuncSetAttribute(k_gemm1, cudaFuncAttributeMaxDynamicSharedMemorySize, SMEM_BYTES);
    cudaFuncSetAttribute(k_gemm2, cudaFuncAttributeMaxDynamicSharedMemorySize, SMEM_BYTES);

    k_convE<<<dim3(PN / 32, PN / 32, BG), dim3(16, 32)>>>(evec, nv, out3);
    k_convX<<<dim3(FF / 32, PN / 32, BG), dim3(16, 32)>>>(x, out0, out2);
    k_gemm1<<<dim3(PN / 128, FF / 128, BG), 256, SMEM_BYTES>>>(nv);
    k_gemm2<<<dim3(FF / 128, PN / 128, BG * 3), 256, SMEM_BYTES>>>(nv, out1);
}

// round 15
// speedup vs baseline: 1.0441x; 1.0441x over previous
#include <cuda_runtime.h>
#include <cuda_fp16.h>
#include <stdint.h>

#define BG 32
#define PN 1024
#define FF 512
#define CC 512

// ---------------------------------------------------------------------------
// Static device scratch: fp16 operand copies (all k-stride = 1024).
// ---------------------------------------------------------------------------
__device__ __half g_Eh [(size_t)BG * PN * PN];  // E   [b][n][p]  (gemm2 A)
__device__ __half g_ETh[(size_t)BG * PN * PN];  // E^T [b][p][n]  (gemm1 B)
__device__ __half g_XTh[(size_t)BG * FF * PN];  // X^T [b][f][n]  (gemm1 A)
__device__ __half g_GTh[(size_t)BG * FF * PN];  // GFT^T [b][f][p] (gemm2 B)

// ---------------------------------------------------------------------------
__device__ __forceinline__ uint32_t smem_u32(const void* p) {
    uint32_t a;
    asm("{ .reg .u64 t; cvta.to.shared.u64 t, %1; cvt.u32.u64 %0, t; }" : "=r"(a) : "l"(p));
    return a;
}
__device__ __forceinline__ void cp16(uint32_t dst, const void* src) {
    asm volatile("{ .reg .u64 g; cvta.to.global.u64 g, %1; "
                 "cp.async.cg.shared.global [%0], [g], 16; }"
                 :: "r"(dst), "l"(src) : "memory");
}
#define CP_COMMIT() asm volatile("cp.async.commit_group;" ::: "memory")
#define CP_WAIT(n)  asm volatile("cp.async.wait_group %0;" :: "n"(n) : "memory")

__device__ __forceinline__ void ldsm_x4(uint32_t* r, uint32_t addr) {
    asm volatile("ldmatrix.sync.aligned.m8n8.x4.shared.b16 {%0,%1,%2,%3}, [%4];"
                 : "=r"(r[0]), "=r"(r[1]), "=r"(r[2]), "=r"(r[3]) : "r"(addr));
}
__device__ __forceinline__ void mma16816(float* d, const uint32_t* a,
                                         uint32_t b0, uint32_t b1) {
    asm volatile("mma.sync.aligned.m16n8k16.row.col.f32.f16.f16.f32 "
                 "{%0,%1,%2,%3}, {%4,%5,%6,%7}, {%8,%9}, {%0,%1,%2,%3};"
                 : "+f"(d[0]), "+f"(d[1]), "+f"(d[2]), "+f"(d[3])
                 : "r"(a[0]), "r"(a[1]), "r"(a[2]), "r"(a[3]), "r"(b0), "r"(b1));
}

// SMEM: 3-stage pipeline; per stage 2 tiles (A, B); tile = 128 rows x 32 fp16,
// padded row stride 80B (conflict-free ldmatrix).
#define RS      80
#define TILE_B  (128 * RS)          // 10240
#define STAGE_B (2 * TILE_B)        // 20480
#define SMEM_BYTES (3 * STAGE_B + 256)

// load one k32 stage: 2 tiles of 128x32 fp16 (gmem row stride 1024 elems)
__device__ __forceinline__ void stage_load(uint32_t sb,
                                           const __half* A, const __half* B,
                                           int k0, int tid) {
    const int r = tid >> 2;          // 0..63
    const int q = tid & 3;           // 16B chunk within 64B row
    const int co = k0 + q * 8;
    #pragma unroll
    for (int h = 0; h < 2; ++h) {
        const int row = r + h * 64;
        const uint32_t so = row * RS + q * 16;
        cp16(sb + 0 * TILE_B + so, A + (size_t)row * 1024 + co);
        cp16(sb + 1 * TILE_B + so, B + (size_t)row * 1024 + co);
    }
}

// one 32-k chunk of single-pass fp16 MMA; warp tile 64(m) x 32(n).
__device__ __forceinline__ void compute_chunk(float acc[4][4][4], uint32_t st,
                                              int m0w, int n0w, int lane) {
    const int lrow = lane & 15;
    const int lcol8 = (lane >> 4) << 3;
    #pragma unroll
    for (int ks = 0; ks < 2; ++ks) {
        const uint32_t cofs = (uint32_t)(ks * 16 + lcol8) * 2;
        uint32_t bh[2][4];
        #pragma unroll
        for (int g = 0; g < 2; ++g)
            ldsm_x4(bh[g], st + TILE_B + (uint32_t)(n0w + g * 16 + lrow) * RS + cofs);
        #pragma unroll
        for (int mi = 0; mi < 4; ++mi) {
            uint32_t ah[4];
            ldsm_x4(ah, st + (uint32_t)(m0w + mi * 16 + lrow) * RS + cofs);
            #pragma unroll
            for (int ni = 0; ni < 4; ++ni) {
                const int g = ni >> 1, o = ni & 1;
                mma16816(acc[mi][ni], ah, bh[g][o], bh[g][o + 2]);
            }
        }
    }
}

// ---------------------------------------------------------------------------
// convE: fp32 E -> fp16 Eh + fp16 ETh, AND fused gather for updated_evectors.
// ---------------------------------------------------------------------------
__global__ void k_convE(const float* __restrict__ E,
                        const int* __restrict__ nv, float* __restrict__ out3) {
    __shared__ float s[32][33];
    const int b = blockIdx.z, n0 = blockIdx.y * 32, p0 = blockIdx.x * 32;
    const int tx = threadIdx.x, ty = threadIdx.y;   // (16, 32)
    float2 v = *(const float2*)(E + ((size_t)b * PN + n0 + ty) * PN + p0 + 2 * tx);
    s[ty][2 * tx] = v.x; s[ty][2 * tx + 1] = v.y;
    size_t off = ((size_t)b * PN + n0 + ty) * PN + p0 + 2 * tx;
    *(__half2*)(g_Eh + off) = __halves2half2(__float2half_rn(v.x), __float2half_rn(v.y));
    __syncthreads();
    float a0 = s[2 * tx][ty], a1 = s[2 * tx + 1][ty];
    size_t off2 = ((size_t)b * PN + p0 + ty) * PN + n0 + 2 * tx;
    *(__half2*)(g_ETh + off2) = __halves2half2(__float2half_rn(a0), __float2half_rn(a1));

    // fused gather (warp wid = candidate slot, lane = n offset)
    const int tid = ty * 16 + tx;
    const int wid = tid >> 5, lane = tid & 31;      // 16 warps
    const float stepv = __fdiv_rn((float)nv[b] - 1.0f, 511.0f);
    int c_lo = (int)floorf(((float)p0 - 1.0f) / stepv) - 1;
    if (c_lo < 0) c_lo = 0;
    int c_hi = (int)ceilf(((float)p0 + 32.0f) / stepv) + 2;
    if (c_hi > CC) c_hi = CC;
    for (int c = c_lo + wid; c < c_hi; c += 16) {
        const int idx = (int)rintf(__fmul_rn((float)c, stepv));
        if (idx >= p0 && idx < p0 + 32)
            out3[((size_t)b * CC + c) * PN + n0 + lane] = s[lane][idx - p0];
    }
}
__global__ void k_convX(const float* __restrict__ X,
                        float* __restrict__ out0, float* __restrict__ out2) {
    __shared__ float s[32][33];
    const int b = blockIdx.z, n0 = blockIdx.y * 32, f0 = blockIdx.x * 32;
    const int tx = threadIdx.x, ty = threadIdx.y;
    const size_t xin = ((size_t)b * PN + n0 + ty) * FF + f0 + 2 * tx;
    float2 v = *(const float2*)(X + xin);
    s[ty][2 * tx] = v.x; s[ty][2 * tx + 1] = v.y;
    // fused copies: n_level_feat and original_x (x3)
    *(float2*)(out0 + xin) = v;
    const size_t rep = ((size_t)b * 3 * PN + n0 + ty) * FF + f0 + 2 * tx;
    *(float2*)(out2 + rep) = v;
    *(float2*)(out2 + rep + (size_t)PN * FF) = v;
    *(float2*)(out2 + rep + (size_t)2 * PN * FF) = v;
    __syncthreads();
    float a0 = s[2 * tx][ty], a1 = s[2 * tx + 1][ty];
    size_t off2 = ((size_t)b * FF + f0 + ty) * PN + n0 + 2 * tx;
    *(__half2*)(g_XTh + off2) = __halves2half2(__float2half_rn(a0), __float2half_rn(a1));
}

// ---------------------------------------------------------------------------
// GEMM1: GT[b][f][p] = sum_n XT[f][n] * ET[p][n]   (m=f, n=p, k=n)
// 3-stage pipeline, one __syncthreads per chunk.
// ---------------------------------------------------------------------------
__global__ __launch_bounds__(256, 2)
void k_gemm1(const int* __restrict__ nv) {
    extern __shared__ char dsm[];
    const uint32_t raw = smem_u32(dsm);
    const uint32_t sb = (raw + 127u) & ~127u;
    const int b = blockIdx.z, f0 = blockIdx.y * 128, p0 = blockIdx.x * 128;
    const int N = nv[b];
    const int tid = threadIdx.x, wid = tid >> 5, lane = tid & 31;
    const int m0w = (wid & 1) * 64, n0w = (wid >> 1) * 32;

    if (p0 >= N) {  // ET rows zero -> GT tile zero
        const uint4 z = make_uint4(0, 0, 0, 0);
        #pragma unroll
        for (int q = 0; q < 8; ++q) {
            int e = q * 256 + tid;
            int r = e >> 4, cchunk = e & 15;
            *(uint4*)(g_GTh + ((size_t)b * FF + f0 + r) * PN + p0 + cchunk * 8) = z;
        }
        return;
    }

    const __half* A = g_XTh + ((size_t)b * FF + f0) * PN;
    const __half* B = g_ETh + ((size_t)b * PN + p0) * PN;
    const int T = (N + 31) >> 5;

    stage_load(sb, A, B, 0, tid); CP_COMMIT();
    if (T > 1) stage_load(sb + STAGE_B, A, B, 32, tid);
    CP_COMMIT();

    float acc[4][4][4];
    #pragma unroll
    for (int i = 0; i < 4; ++i)
        #pragma unroll
        for (int j = 0; j < 4; ++j)
            #pragma unroll
            for (int r = 0; r < 4; ++r) acc[i][j][r] = 0.0f;

    int cur = 0, nxt = 2;   // stage indices mod 3
    for (int t = 0; t < T; ++t) {
        CP_WAIT(1);
        __syncthreads();   // all warps done with stage (t-1); stage t resident
        if (t + 2 < T) stage_load(sb + nxt * STAGE_B, A, B, (t + 2) << 5, tid);
        CP_COMMIT();
        compute_chunk(acc, sb + cur * STAGE_B, m0w, n0w, lane);
        cur = (cur == 2) ? 0 : cur + 1;
        nxt = (nxt == 2) ? 0 : nxt + 1;
    }

    #pragma unroll
    for (int mi = 0; mi < 4; ++mi)
        #pragma unroll
        for (int ni = 0; ni < 4; ++ni)
            #pragma unroll
            for (int h = 0; h < 2; ++h) {
                const int f = f0 + m0w + mi * 16 + (lane >> 2) + h * 8;
                const int p = p0 + n0w + ni * 8 + (lane & 3) * 2;
                const float c0 = acc[mi][ni][h * 2], c1 = acc[mi][ni][h * 2 + 1];
                *(__half2*)(g_GTh + ((size_t)b * FF + f) * PN + p) =
                    __halves2half2(__float2half_rn(c0), __float2half_rn(c1));
            }
}

// ---------------------------------------------------------------------------
// GEMM2: out1[b*3+kid][n][f] = sum_{p in [lo,hi)} E[n][p] * GT[f][p]
// LPT scheduling: blockIdx.z in [0,32) -> split 2 (longest k-range) first,
// [32,64) -> split 1, [64,96) -> split 0. CTAs rasterize z-slowest, so the
// long CTAs launch in the first waves and short ones pack the tail.
// ---------------------------------------------------------------------------
__global__ __launch_bounds__(256, 2)
void k_gemm2(const int* __restrict__ nv, float* __restrict__ out1) {
    extern __shared__ char dsm[];
    const int zz = blockIdx.z;
    const int b = zz & 31;
    const int kid = 2 - (zz >> 5);     // z-group 0 -> split2, 1 -> split1, 2 -> split0
    const int bz = b * 3 + kid;        // output slab index
    const int n0 = blockIdx.y * 128, f0 = blockIdx.x * 128;
    const int N = nv[b];
    const int tid = threadIdx.x, wid = tid >> 5, lane = tid & 31;

    if (n0 >= N) {  // zero tile
        const uint4 z = make_uint4(0, 0, 0, 0);
        #pragma unroll
        for (int q = 0; q < 16; ++q) {
            int e = q * 256 + tid;
            int r = e >> 5, cchunk = e & 31;
            *(uint4*)(out1 + ((size_t)bz * PN + n0 + r) * FF + f0 + cchunk * 4) = z;
        }
        return;
    }

    const float nf = (float)N;
    const int s1 = (int)ceilf(__fmul_rn(nf, 0.1f));
    const int s2 = (int)ceilf(__fmul_rn(__fmul_rn(nf, 0.1f), 2.0f));
    const int lo = (kid == 0) ? 0  : (kid == 1 ? s1      : s1 + s2);
    const int hi = (kid == 0) ? s1 : (kid == 1 ? s1 + s2 : N);
    const int kstart = lo & ~31;
    const int T = (hi - kstart + 31) >> 5;

    const uint32_t raw = smem_u32(dsm);
    const uint32_t sb = (raw + 127u) & ~127u;
    const int m0w = (wid & 1) * 64, n0w = (wid >> 1) * 32;

    const __half* A = g_Eh  + ((size_t)b * PN + n0) * PN;
    const __half* B = g_GTh + ((size_t)b * FF + f0) * PN;

    stage_load(sb, A, B, kstart, tid); CP_COMMIT();
    if (T > 1) stage_load(sb + STAGE_B, A, B, kstart + 32, tid);
    CP_COMMIT();

    float acc[4][4][4];
    #pragma unroll
    for (int i = 0; i < 4; ++i)
        #pragma unroll
        for (int j = 0; j < 4; ++j)
            #pragma unroll
            for (int r = 0; r < 4; ++r) acc[i][j][r] = 0.0f;

    int cur = 0, nxt = 2;
    for (int t = 0; t < T; ++t) {
        CP_WAIT(1);
        __syncthreads();
        if (t + 2 < T) stage_load(sb + nxt * STAGE_B, A, B, kstart + ((t + 2) << 5), tid);
        CP_COMMIT();
        const int kg0 = kstart + (t << 5);
        // mask B (one zero factor suffices) at the [lo,hi) edges
        if (kg0 < lo || kg0 + 32 > hi) {
            const uint32_t st = sb + cur * STAGE_B;
            for (int e = tid; e < 128 * 32; e += 256) {
                const int r = e >> 5, c = e & 31;
                const int k = kg0 + c;
                if (k < lo || k >= hi) {
                    const uint32_t a = st + TILE_B + (uint32_t)r * RS + c * 2;
                    asm volatile("st.shared.u16 [%0], 0;" :: "r"(a) : "memory");
                }
            }
            __syncthreads();
        }
        compute_chunk(acc, sb + cur * STAGE_B, m0w, n0w, lane);
        cur = (cur == 2) ? 0 : cur + 1;
        nxt = (nxt == 2) ? 0 : nxt + 1;
    }

    #pragma unroll
    for (int mi = 0; mi < 4; ++mi)
        #pragma unroll
        for (int ni = 0; ni < 4; ++ni)
            #pragma unroll
            for (int h = 0; h < 2; ++h) {
                const int n = n0 + m0w + mi * 16 + (lane >> 2) + h * 8;
                const int f = f0 + n0w + ni * 8 + (lane & 3) * 2;
                float2 v = make_float2(acc[mi][ni][h * 2], acc[mi][ni][h * 2 + 1]);
                *(float2*)(out1 + ((size_t)bz * PN + n) * FF + f) = v;
            }
}

// ---------------------------------------------------------------------------
extern "C" void kernel_launch(void* const* d_in, const int* in_sizes, int n_in,
                              void* d_out, int out_size) {
    const float* x = nullptr;
    const float* evec = nullptr;
    const int*   nv = nullptr;
    for (int i = 0; i < n_in; ++i) {
        if      (in_sizes[i] == BG * PN * FF) x    = (const float*)d_in[i];
        else if (in_sizes[i] == BG * PN * PN) evec = (const float*)d_in[i];
        else if (in_sizes[i] == BG)           nv   = (const int*)d_in[i];
    }
    float* out  = (float*)d_out;
    float* out0 = out;                              // n_level_feat  [B,P,F]
    float* out1 = out0 + (size_t)BG * PN * FF;      // x_updated     [B,3,P,F]
    float* out2 = out1 + (size_t)BG * 3 * PN * FF;  // original_x    [B,3,P,F]
    float* out3 = out2 + (size_t)BG * 3 * PN * FF;  // updated_evecs [B,C,P]

    cudaFuncSetAttribute(k_gemm1, cudaFuncAttributeMaxDynamicSharedMemorySize, SMEM_BYTES);
    cudaFuncSetAttribute(k_gemm2, cudaFuncAttributeMaxDynamicSharedMemorySize, SMEM_BYTES);

    k_convE<<<dim3(PN / 32, PN / 32, BG), dim3(16, 32)>>>(evec, nv, out3);
    k_convX<<<dim3(FF / 32, PN / 32, BG), dim3(16, 32)>>>(x, out0, out2);
    k_gemm1<<<dim3(PN / 128, FF / 128, BG), 256, SMEM_BYTES>>>(nv);
    k_gemm2<<<dim3(FF / 128, PN / 128, BG * 3), 256, SMEM_BYTES>>>(nv, out1);
}

// round 16
// speedup vs baseline: 1.1445x; 1.0962x over previous
#include <cuda_runtime.h>
#include <cuda_fp16.h>
#include <stdint.h>

#define BG 32
#define PN 1024
#define FF 512
#define CC 512

// ---------------------------------------------------------------------------
// Static device scratch: fp16 operand copies (all k-stride = 1024).
// Zero-initialized at context init; tiles entirely beyond N are never written
// (their true value is zero), so skipping them is exact.
// ---------------------------------------------------------------------------
__device__ __half g_Eh [(size_t)BG * PN * PN];  // E   [b][n][p]  (gemm2 A)
__device__ __half g_ETh[(size_t)BG * PN * PN];  // E^T [b][p][n]  (gemm1 B)
__device__ __half g_XTh[(size_t)BG * FF * PN];  // X^T [b][f][n]  (gemm1 A)
__device__ __half g_GTh[(size_t)BG * FF * PN];  // GFT^T [b][f][p] (gemm2 B)

// ---------------------------------------------------------------------------
__device__ __forceinline__ uint32_t smem_u32(const void* p) {
    uint32_t a;
    asm("{ .reg .u64 t; cvta.to.shared.u64 t, %1; cvt.u32.u64 %0, t; }" : "=r"(a) : "l"(p));
    return a;
}
__device__ __forceinline__ void cp16(uint32_t dst, const void* src) {
    asm volatile("{ .reg .u64 g; cvta.to.global.u64 g, %1; "
                 "cp.async.cg.shared.global [%0], [g], 16; }"
                 :: "r"(dst), "l"(src) : "memory");
}
#define CP_COMMIT() asm volatile("cp.async.commit_group;" ::: "memory")
#define CP_WAIT(n)  asm volatile("cp.async.wait_group %0;" :: "n"(n) : "memory")

__device__ __forceinline__ void ldsm_x4(uint32_t* r, uint32_t addr) {
    asm volatile("ldmatrix.sync.aligned.m8n8.x4.shared.b16 {%0,%1,%2,%3}, [%4];"
                 : "=r"(r[0]), "=r"(r[1]), "=r"(r[2]), "=r"(r[3]) : "r"(addr));
}
__device__ __forceinline__ void mma16816(float* d, const uint32_t* a,
                                         uint32_t b0, uint32_t b1) {
    asm volatile("mma.sync.aligned.m16n8k16.row.col.f32.f16.f16.f32 "
                 "{%0,%1,%2,%3}, {%4,%5,%6,%7}, {%8,%9}, {%0,%1,%2,%3};"
                 : "+f"(d[0]), "+f"(d[1]), "+f"(d[2]), "+f"(d[3])
                 : "r"(a[0]), "r"(a[1]), "r"(a[2]), "r"(a[3]), "r"(b0), "r"(b1));
}

// SMEM: 3-stage pipeline; per stage 2 tiles (A, B); tile = 128 rows x 32 fp16,
// padded row stride 80B (conflict-free ldmatrix).
#define RS      80
#define TILE_B  (128 * RS)          // 10240
#define STAGE_B (2 * TILE_B)        // 20480
#define SMEM_BYTES (3 * STAGE_B + 256)

// load one k32 stage: 2 tiles of 128x32 fp16 (gmem row stride 1024 elems)
__device__ __forceinline__ void stage_load(uint32_t sb,
                                           const __half* A, const __half* B,
                                           int k0, int tid) {
    const int r = tid >> 2;          // 0..63
    const int q = tid & 3;           // 16B chunk within 64B row
    const int co = k0 + q * 8;
    #pragma unroll
    for (int h = 0; h < 2; ++h) {
        const int row = r + h * 64;
        const uint32_t so = row * RS + q * 16;
        cp16(sb + 0 * TILE_B + so, A + (size_t)row * 1024 + co);
        cp16(sb + 1 * TILE_B + so, B + (size_t)row * 1024 + co);
    }
}

// one 32-k chunk of single-pass fp16 MMA; warp tile 64(m) x 32(n).
__device__ __forceinline__ void compute_chunk(float acc[4][4][4], uint32_t st,
                                              int m0w, int n0w, int lane) {
    const int lrow = lane & 15;
    const int lcol8 = (lane >> 4) << 3;
    #pragma unroll
    for (int ks = 0; ks < 2; ++ks) {
        const uint32_t cofs = (uint32_t)(ks * 16 + lcol8) * 2;
        uint32_t bh[2][4];
        #pragma unroll
        for (int g = 0; g < 2; ++g)
            ldsm_x4(bh[g], st + TILE_B + (uint32_t)(n0w + g * 16 + lrow) * RS + cofs);
        #pragma unroll
        for (int mi = 0; mi < 4; ++mi) {
            uint32_t ah[4];
            ldsm_x4(ah, st + (uint32_t)(m0w + mi * 16 + lrow) * RS + cofs);
            #pragma unroll
            for (int ni = 0; ni < 4; ++ni) {
                const int g = ni >> 1, o = ni & 1;
                mma16816(acc[mi][ni], ah, bh[g][o], bh[g][o + 2]);
            }
        }
    }
}

// ---------------------------------------------------------------------------
// convE: fp32 E -> fp16 Eh + fp16 ETh, AND fused gather for updated_evectors.
// N-truncated: tiles with p0>=N have no work (scratch pre-zeroed, no gather
// columns since idx<=N-1<p0); tiles with n0>=N only zero-fill gather output.
// ---------------------------------------------------------------------------
__global__ void k_convE(const float* __restrict__ E,
                        const int* __restrict__ nv, float* __restrict__ out3) {
    __shared__ float s[32][33];
    const int b = blockIdx.z, n0 = blockIdx.y * 32, p0 = blockIdx.x * 32;
    const int N = nv[b];
    if (p0 >= N) return;
    const int tx = threadIdx.x, ty = threadIdx.y;   // (16, 32)
    const int tid = ty * 16 + tx;
    const int wid = tid >> 5, lane = tid & 31;      // 16 warps
    const float stepv = __fdiv_rn((float)N - 1.0f, 511.0f);
    int c_lo = (int)floorf(((float)p0 - 1.0f) / stepv) - 1;
    if (c_lo < 0) c_lo = 0;
    int c_hi = (int)ceilf(((float)p0 + 32.0f) / stepv) + 2;
    if (c_hi > CC) c_hi = CC;

    if (n0 >= N) {   // E rows zero: only the gather output must be written
        for (int c = c_lo + wid; c < c_hi; c += 16) {
            const int idx = (int)rintf(__fmul_rn((float)c, stepv));
            if (idx >= p0 && idx < p0 + 32)
                out3[((size_t)b * CC + c) * PN + n0 + lane] = 0.0f;
        }
        return;
    }

    float2 v = *(const float2*)(E + ((size_t)b * PN + n0 + ty) * PN + p0 + 2 * tx);
    s[ty][2 * tx] = v.x; s[ty][2 * tx + 1] = v.y;
    size_t off = ((size_t)b * PN + n0 + ty) * PN + p0 + 2 * tx;
    *(__half2*)(g_Eh + off) = __halves2half2(__float2half_rn(v.x), __float2half_rn(v.y));
    __syncthreads();
    float a0 = s[2 * tx][ty], a1 = s[2 * tx + 1][ty];
    size_t off2 = ((size_t)b * PN + p0 + ty) * PN + n0 + 2 * tx;
    *(__half2*)(g_ETh + off2) = __halves2half2(__float2half_rn(a0), __float2half_rn(a1));

    // fused gather (warp wid = candidate slot, lane = n offset)
    for (int c = c_lo + wid; c < c_hi; c += 16) {
        const int idx = (int)rintf(__fmul_rn((float)c, stepv));
        if (idx >= p0 && idx < p0 + 32)
            out3[((size_t)b * CC + c) * PN + n0 + lane] = s[lane][idx - p0];
    }
}
__global__ void k_convX(const float* __restrict__ X, const int* __restrict__ nv,
                        float* __restrict__ out0, float* __restrict__ out2) {
    __shared__ float s[32][33];
    const int b = blockIdx.z, n0 = blockIdx.y * 32, f0 = blockIdx.x * 32;
    const int tx = threadIdx.x, ty = threadIdx.y;
    const int N = nv[b];
    const size_t xin = ((size_t)b * PN + n0 + ty) * FF + f0 + 2 * tx;
    const size_t rep = ((size_t)b * 3 * PN + n0 + ty) * FF + f0 + 2 * tx;

    if (n0 >= N) {   // X rows zero: outputs must still be written (poisoned)
        const float2 z = make_float2(0.0f, 0.0f);
        *(float2*)(out0 + xin) = z;
        *(float2*)(out2 + rep) = z;
        *(float2*)(out2 + rep + (size_t)PN * FF) = z;
        *(float2*)(out2 + rep + (size_t)2 * PN * FF) = z;
        return;      // XTh rows stay zero-initialized
    }

    float2 v = *(const float2*)(X + xin);
    s[ty][2 * tx] = v.x; s[ty][2 * tx + 1] = v.y;
    // fused copies: n_level_feat and original_x (x3)
    *(float2*)(out0 + xin) = v;
    *(float2*)(out2 + rep) = v;
    *(float2*)(out2 + rep + (size_t)PN * FF) = v;
    *(float2*)(out2 + rep + (size_t)2 * PN * FF) = v;
    __syncthreads();
    float a0 = s[2 * tx][ty], a1 = s[2 * tx + 1][ty];
    size_t off2 = ((size_t)b * FF + f0 + ty) * PN + n0 + 2 * tx;
    *(__half2*)(g_XTh + off2) = __halves2half2(__float2half_rn(a0), __float2half_rn(a1));
}

// ---------------------------------------------------------------------------
// GEMM1: GT[b][f][p] = sum_n XT[f][n] * ET[p][n]   (m=f, n=p, k=n)
// 3-stage pipeline, one __syncthreads per chunk.
// ---------------------------------------------------------------------------
__global__ __launch_bounds__(256, 2)
void k_gemm1(const int* __restrict__ nv) {
    extern __shared__ char dsm[];
    const uint32_t raw = smem_u32(dsm);
    const uint32_t sb = (raw + 127u) & ~127u;
    const int b = blockIdx.z, f0 = blockIdx.y * 128, p0 = blockIdx.x * 128;
    const int N = nv[b];
    const int tid = threadIdx.x, wid = tid >> 5, lane = tid & 31;
    const int m0w = (wid & 1) * 64, n0w = (wid >> 1) * 32;

    if (p0 >= N) {  // ET rows zero -> GT tile zero
        const uint4 z = make_uint4(0, 0, 0, 0);
        #pragma unroll
        for (int q = 0; q < 8; ++q) {
            int e = q * 256 + tid;
            int r = e >> 4, cchunk = e & 15;
            *(uint4*)(g_GTh + ((size_t)b * FF + f0 + r) * PN + p0 + cchunk * 8) = z;
        }
        return;
    }

    const __half* A = g_XTh + ((size_t)b * FF + f0) * PN;
    const __half* B = g_ETh + ((size_t)b * PN + p0) * PN;
    const int T = (N + 31) >> 5;

    stage_load(sb, A, B, 0, tid); CP_COMMIT();
    if (T > 1) stage_load(sb + STAGE_B, A, B, 32, tid);
    CP_COMMIT();

    float acc[4][4][4];
    #pragma unroll
    for (int i = 0; i < 4; ++i)
        #pragma unroll
        for (int j = 0; j < 4; ++j)
            #pragma unroll
            for (int r = 0; r < 4; ++r) acc[i][j][r] = 0.0f;

    int cur = 0, nxt = 2;   // stage indices mod 3
    for (int t = 0; t < T; ++t) {
        CP_WAIT(1);
        __syncthreads();   // all warps done with stage (t-1); stage t resident
        if (t + 2 < T) stage_load(sb + nxt * STAGE_B, A, B, (t + 2) << 5, tid);
        CP_COMMIT();
        compute_chunk(acc, sb + cur * STAGE_B, m0w, n0w, lane);
        cur = (cur == 2) ? 0 : cur + 1;
        nxt = (nxt == 2) ? 0 : nxt + 1;
    }

    #pragma unroll
    for (int mi = 0; mi < 4; ++mi)
        #pragma unroll
        for (int ni = 0; ni < 4; ++ni)
            #pragma unroll
            for (int h = 0; h < 2; ++h) {
                const int f = f0 + m0w + mi * 16 + (lane >> 2) + h * 8;
                const int p = p0 + n0w + ni * 8 + (lane & 3) * 2;
                const float c0 = acc[mi][ni][h * 2], c1 = acc[mi][ni][h * 2 + 1];
                *(__half2*)(g_GTh + ((size_t)b * FF + f) * PN + p) =
                    __halves2half2(__float2half_rn(c0), __float2half_rn(c1));
            }
}

// ---------------------------------------------------------------------------
// GEMM2: out1[b*3+kid][n][f] = sum_{p in [lo,hi)} E[n][p] * GT[f][p]
// LPT scheduling: blockIdx.z in [0,32) -> split 2 (longest k-range) first,
// [32,64) -> split 1, [64,96) -> split 0.
// ---------------------------------------------------------------------------
__global__ __launch_bounds__(256, 2)
void k_gemm2(const int* __restrict__ nv, float* __restrict__ out1) {
    extern __shared__ char dsm[];
    const int zz = blockIdx.z;
    const int b = zz & 31;
    const int kid = 2 - (zz >> 5);     // z-group 0 -> split2, 1 -> split1, 2 -> split0
    const int bz = b * 3 + kid;        // output slab index
    const int n0 = blockIdx.y * 128, f0 = blockIdx.x * 128;
    const int N = nv[b];
    const int tid = threadIdx.x, wid = tid >> 5, lane = tid & 31;

    if (n0 >= N) {  // zero tile
        const uint4 z = make_uint4(0, 0, 0, 0);
        #pragma unroll
        for (int q = 0; q < 16; ++q) {
            int e = q * 256 + tid;
            int r = e >> 5, cchunk = e & 31;
            *(uint4*)(out1 + ((size_t)bz * PN + n0 + r) * FF + f0 + cchunk * 4) = z;
        }
        return;
    }

    const float nf = (float)N;
    const int s1 = (int)ceilf(__fmul_rn(nf, 0.1f));
    const int s2 = (int)ceilf(__fmul_rn(__fmul_rn(nf, 0.1f), 2.0f));
    const int lo = (kid == 0) ? 0  : (kid == 1 ? s1      : s1 + s2);
    const int hi = (kid == 0) ? s1 : (kid == 1 ? s1 + s2 : N);
    const int kstart = lo & ~31;
    const int T = (hi - kstart + 31) >> 5;

    const uint32_t raw = smem_u32(dsm);
    const uint32_t sb = (raw + 127u) & ~127u;
    const int m0w = (wid & 1) * 64, n0w = (wid >> 1) * 32;

    const __half* A = g_Eh  + ((size_t)b * PN + n0) * PN;
    const __half* B = g_GTh + ((size_t)b * FF + f0) * PN;

    stage_load(sb, A, B, kstart, tid); CP_COMMIT();
    if (T > 1) stage_load(sb + STAGE_B, A, B, kstart + 32, tid);
    CP_COMMIT();

    float acc[4][4][4];
    #pragma unroll
    for (int i = 0; i < 4; ++i)
        #pragma unroll
        for (int j = 0; j < 4; ++j)
            #pragma unroll
            for (int r = 0; r < 4; ++r) acc[i][j][r] = 0.0f;

    int cur = 0, nxt = 2;
    for (int t = 0; t < T; ++t) {
        CP_WAIT(1);
        __syncthreads();
        if (t + 2 < T) stage_load(sb + nxt * STAGE_B, A, B, kstart + ((t + 2) << 5), tid);
        CP_COMMIT();
        const int kg0 = kstart + (t << 5);
        // mask B (one zero factor suffices) at the [lo,hi) edges
        if (kg0 < lo || kg0 + 32 > hi) {
            const uint32_t st = sb + cur * STAGE_B;
            for (int e = tid; e < 128 * 32; e += 256) {
                const int r = e >> 5, c = e & 31;
                const int k = kg0 + c;
                if (k < lo || k >= hi) {
                    const uint32_t a = st + TILE_B + (uint32_t)r * RS + c * 2;
                    asm volatile("st.shared.u16 [%0], 0;" :: "r"(a) : "memory");
                }
            }
            __syncthreads();
        }
        compute_chunk(acc, sb + cur * STAGE_B, m0w, n0w, lane);
        cur = (cur == 2) ? 0 : cur + 1;
        nxt = (nxt == 2) ? 0 : nxt + 1;
    }

    #pragma unroll
    for (int mi = 0; mi < 4; ++mi)
        #pragma unroll
        for (int ni = 0; ni < 4; ++ni)
            #pragma unroll
            for (int h = 0; h < 2; ++h) {
                const int n = n0 + m0w + mi * 16 + (lane >> 2) + h * 8;
                const int f = f0 + n0w + ni * 8 + (lane & 3) * 2;
                float2 v = make_float2(acc[mi][ni][h * 2], acc[mi][ni][h * 2 + 1]);
                *(float2*)(out1 + ((size_t)bz * PN + n) * FF + f) = v;
            }
}

// ---------------------------------------------------------------------------
extern "C" void kernel_launch(void* const* d_in, const int* in_sizes, int n_in,
                              void* d_out, int out_size) {
    const float* x = nullptr;
    const float* evec = nullptr;
    const int*   nv = nullptr;
    for (int i = 0; i < n_in; ++i) {
        if      (in_sizes[i] == BG * PN * FF) x    = (const float*)d_in[i];
        else if (in_sizes[i] == BG * PN * PN) evec = (const float*)d_in[i];
        else if (in_sizes[i] == BG)           nv   = (const int*)d_in[i];
    }
    float* out  = (float*)d_out;
    float* out0 = out;                              // n_level_feat  [B,P,F]
    float* out1 = out0 + (size_t)BG * PN * FF;      // x_updated     [B,3,P,F]
    float* out2 = out1 + (size_t)BG * 3 * PN * FF;  // original_x    [B,3,P,F]
    float* out3 = out2 + (size_t)BG * 3 * PN * FF;  // updated_evecs [B,C,P]

    cudaFuncSetAttribute(k_gemm1, cudaFuncAttributeMaxDynamicSharedMemorySize, SMEM_BYTES);
    cudaFuncSetAttribute(k_gemm2, cudaFuncAttributeMaxDynamicSharedMemorySize, SMEM_BYTES);

    k_convE<<<dim3(PN / 32, PN / 32, BG), dim3(16, 32)>>>(evec, nv, out3);
    k_convX<<<dim3(FF / 32, PN / 32, BG), dim3(16, 32)>>>(x, nv, out0, out2);
    k_gemm1<<<dim3(PN / 128, FF / 128, BG), 256, SMEM_BYTES>>>(nv);
    k_gemm2<<<dim3(FF / 128, PN / 128, BG * 3), 256, SMEM_BYTES>>>(nv, out1);
}